// round 1
// baseline (speedup 1.0000x reference)
#include <cuda_runtime.h>
#include <cmath>

#define HID  640
#define ADIM 128
#define WPB  160     // warps per batch in pass1
#define MAXB 16

// ---- device scratch (no allocations allowed) ----
__device__ float g_r[MAXB * HID];                 // r[b] = scale * Wk^T (Wq pos[b])
__device__ float g_pacc[(size_t)MAXB * WPB * HID]; // per-warp partial weighted sums
__device__ float g_pm[MAXB * WPB];                // per-warp running max
__device__ float g_ps[MAXB * WPB];                // per-warp running sum of exp

// ---------------------------------------------------------------------------
// Kernel 1: r[b,h] = scale * sum_a Wk[a,h] * (sum_h' Wq[a,h'] * pos[b,h'])
// ---------------------------------------------------------------------------
__global__ void k_compute_r(const float* __restrict__ pos,
                            const float* __restrict__ Wq,
                            const float* __restrict__ Wk,
                            float scale) {
    int b = blockIdx.x;
    int t = threadIdx.x;                // 640 threads
    __shared__ float ps[HID];
    __shared__ float q[ADIM];
    ps[t] = pos[b * HID + t];
    __syncthreads();
    if (t < ADIM) {
        float a = 0.f;
        const float* w = Wq + t * HID;
        #pragma unroll 8
        for (int h = 0; h < HID; h++) a += w[h] * ps[h];
        q[t] = a;
    }
    __syncthreads();
    float a = 0.f;
    #pragma unroll 8
    for (int k = 0; k < ADIM; k++) a += Wk[k * HID + t] * q[k];
    g_r[b * HID + t] = a * scale;
}

// ---------------------------------------------------------------------------
// Kernel 2: streaming pass over gene_hiddens. One warp owns a contiguous row
// range; online-softmax weighted accumulation into 20 regs/lane (640/warp).
// ---------------------------------------------------------------------------
__global__ void __launch_bounds__(256) k_pass1(const float* __restrict__ gh,
                                               int B, int N) {
    int wg   = blockIdx.x * 8 + (threadIdx.x >> 5);
    int b    = wg / WPB;
    int w    = wg % WPB;
    if (b >= B) return;
    int lane = threadIdx.x & 31;

    int rpw = (N + WPB - 1) / WPB;
    int n0  = w * rpw;
    int n1  = min(N, n0 + rpw);

    const float4* rb = reinterpret_cast<const float4*>(g_r + b * HID);
    float4 rr[5], acc[5];
    #pragma unroll
    for (int k = 0; k < 5; k++) {
        rr[k]  = rb[lane + 32 * k];
        acc[k] = make_float4(0.f, 0.f, 0.f, 0.f);
    }

    float m = -1e30f, s = 0.f;
    const float4* base = reinterpret_cast<const float4*>(gh) + (size_t)b * N * (HID / 4);

    for (int n = n0; n < n1; n++) {
        const float4* p = base + (size_t)n * (HID / 4);
        float4 hv[5];
        #pragma unroll
        for (int k = 0; k < 5; k++) hv[k] = p[lane + 32 * k];

        float d = 0.f;
        #pragma unroll
        for (int k = 0; k < 5; k++)
            d += hv[k].x * rr[k].x + hv[k].y * rr[k].y
               + hv[k].z * rr[k].z + hv[k].w * rr[k].w;
        #pragma unroll
        for (int o = 16; o > 0; o >>= 1) d += __shfl_xor_sync(0xffffffffu, d, o);

        if (d > m) {
            float c = __expf(m - d);   // first iter: exp(-huge) = 0
            s *= c;
            #pragma unroll
            for (int k = 0; k < 5; k++) {
                acc[k].x *= c; acc[k].y *= c; acc[k].z *= c; acc[k].w *= c;
            }
            m = d;
        }
        float wt = __expf(d - m);
        s += wt;
        #pragma unroll
        for (int k = 0; k < 5; k++) {
            acc[k].x += wt * hv[k].x; acc[k].y += wt * hv[k].y;
            acc[k].z += wt * hv[k].z; acc[k].w += wt * hv[k].w;
        }
    }

    float4* pa = reinterpret_cast<float4*>(g_pacc + (size_t)(b * WPB + w) * HID);
    #pragma unroll
    for (int k = 0; k < 5; k++) pa[lane + 32 * k] = acc[k];
    if (lane == 0) { g_pm[b * WPB + w] = m; g_ps[b * WPB + w] = s; }
}

// ---------------------------------------------------------------------------
// Kernel 3: per-batch combine + Wv matvec + LayerNorm
// ---------------------------------------------------------------------------
__device__ __forceinline__ float block_sum_640(float v, float* sred, int t) {
    int lane = t & 31, wid = t >> 5;            // 20 warps
    #pragma unroll
    for (int o = 16; o > 0; o >>= 1) v += __shfl_xor_sync(0xffffffffu, v, o);
    if (lane == 0) sred[wid] = v;
    __syncthreads();
    if (wid == 0) {
        float x = (lane < 20) ? sred[lane] : 0.f;
        #pragma unroll
        for (int o = 16; o > 0; o >>= 1) x += __shfl_xor_sync(0xffffffffu, x, o);
        if (lane == 0) sred[0] = x;
    }
    __syncthreads();
    float r = sred[0];
    __syncthreads();
    return r;
}

__global__ void __launch_bounds__(640) k_pass2(const float* __restrict__ Wv,
                                               const float* __restrict__ gamma,
                                               const float* __restrict__ beta,
                                               float* __restrict__ out) {
    int b = blockIdx.x;
    int t = threadIdx.x;                // 640 threads = 20 warps
    int lane = t & 31, wid = t >> 5;

    __shared__ float sred[32];
    __shared__ float wsm[WPB];
    __shared__ float pooled[HID];
    __shared__ float yv[HID];

    // ---- global max over 160 partial maxima ----
    float mv = (t < WPB) ? g_pm[b * WPB + t] : -1e30f;
    #pragma unroll
    for (int o = 16; o > 0; o >>= 1)
        mv = fmaxf(mv, __shfl_xor_sync(0xffffffffu, mv, o));
    if (lane == 0) sred[wid] = mv;
    __syncthreads();
    if (wid == 0) {
        float x = (lane < 20) ? sred[lane] : -1e30f;
        #pragma unroll
        for (int o = 16; o > 0; o >>= 1)
            x = fmaxf(x, __shfl_xor_sync(0xffffffffu, x, o));
        if (lane == 0) sred[0] = x;
    }
    __syncthreads();
    float M = sred[0];
    __syncthreads();

    // ---- per-partial rescale weights + total softmax denominator ----
    float sv = 0.f;
    if (t < WPB) {
        float wv_ = __expf(g_pm[b * WPB + t] - M);
        wsm[t] = wv_;
        sv = wv_ * g_ps[b * WPB + t];
    }
    float S = block_sum_640(sv, sred, t);

    // ---- pooled[h] = (1/S) * sum_i wsm[i] * pacc[b,i,h] ----
    float a = 0.f;
    const float* pa = g_pacc + (size_t)b * WPB * HID + t;
    #pragma unroll 4
    for (int i = 0; i < WPB; i++) a += wsm[i] * pa[(size_t)i * HID];
    pooled[t] = a / S;
    __syncthreads();

    // ---- y[v] = sum_h pooled[h] * Wv[v,h]  (one warp per output v) ----
    for (int v = wid * 32; v < wid * 32 + 32; v++) {
        const float* wr = Wv + (size_t)v * HID;
        float acc2 = 0.f;
        #pragma unroll
        for (int h = lane; h < HID; h += 32) acc2 += pooled[h] * wr[h];
        #pragma unroll
        for (int o = 16; o > 0; o >>= 1)
            acc2 += __shfl_xor_sync(0xffffffffu, acc2, o);
        if (lane == 0) yv[v] = acc2;
    }
    __syncthreads();

    // ---- LayerNorm over 640 ----
    float x = yv[t];
    float mean = block_sum_640(x, sred, t) * (1.f / HID);
    float dx = x - mean;
    float var = block_sum_640(dx * dx, sred, t) * (1.f / HID);
    out[b * HID + t] = dx * rsqrtf(var + 1e-5f) * gamma[t] + beta[t];
}

// ---------------------------------------------------------------------------
extern "C" void kernel_launch(void* const* d_in, const int* in_sizes, int n_in,
                              void* d_out, int out_size) {
    const float* gh    = (const float*)d_in[0];
    const float* pos   = (const float*)d_in[1];
    const float* Wq    = (const float*)d_in[2];
    const float* Wk    = (const float*)d_in[3];
    const float* Wv    = (const float*)d_in[4];
    const float* gamma = (const float*)d_in[5];
    const float* beta  = (const float*)d_in[6];
    float* out = (float*)d_out;

    int B = in_sizes[1] / HID;             // 16
    int N = in_sizes[0] / (B * HID);       // 20000
    float scale = 1.0f / sqrtf((float)ADIM);

    k_compute_r<<<B, HID>>>(pos, Wq, Wk, scale);

    int total_warps = B * WPB;             // 2560
    int blocks = (total_warps + 7) / 8;    // 320 blocks of 8 warps
    k_pass1<<<blocks, 256>>>(gh, B, N);

    k_pass2<<<B, HID>>>(Wv, gamma, beta, out);
}

// round 2
// speedup vs baseline: 1.3178x; 1.3178x over previous
#include <cuda_runtime.h>
#include <cmath>

#define HID  640
#define ADIM 128
#define WPB  148     // warps per batch in pass1 -> 16*148/8 = 296 blocks = 2/SM
#define MAXB 16

// ---- device scratch (no allocations allowed) ----
__device__ float g_q[MAXB * ADIM];                  // q[b] = Wq @ pos[b]
__device__ float g_r[MAXB * HID];                   // r[b] = scale * Wk^T q[b]
__device__ float g_pacc[(size_t)MAXB * WPB * HID];  // per-warp partial weighted sums
__device__ float g_pm[MAXB * WPB];                  // per-warp running max
__device__ float g_ps[MAXB * WPB];                  // per-warp running sum of exp

// ---------------------------------------------------------------------------
// Kernel 1a: q[b,a] = dot(Wq[a,:], pos[b,:])   — one warp per output
// 2048 outputs -> 256 blocks x 256 threads (8 warps)
// ---------------------------------------------------------------------------
__global__ void __launch_bounds__(256) k_q(const float* __restrict__ pos,
                                           const float* __restrict__ Wq) {
    int gw   = blockIdx.x * 8 + (threadIdx.x >> 5);   // 0..2047
    int lane = threadIdx.x & 31;
    int b = gw >> 7;          // /128
    int a = gw & 127;

    const float* wr = Wq + (size_t)a * HID;
    const float* pr = pos + (size_t)b * HID;
    float s = 0.f;
    #pragma unroll
    for (int k = 0; k < HID / 32; k++) {
        int h = lane + 32 * k;
        s += wr[h] * pr[h];
    }
    #pragma unroll
    for (int o = 16; o > 0; o >>= 1) s += __shfl_xor_sync(0xffffffffu, s, o);
    if (lane == 0) g_q[b * ADIM + a] = s;
}

// ---------------------------------------------------------------------------
// Kernel 1b: r[b,h] = scale * sum_a Wk[a,h] * q[b,a]
// grid = (16 b) x (4 h-chunks), block = 160 threads; coalesced over h
// ---------------------------------------------------------------------------
__global__ void __launch_bounds__(160) k_r(const float* __restrict__ Wk,
                                           float scale) {
    int b = blockIdx.x;
    int h = blockIdx.y * 160 + threadIdx.x;

    __shared__ float qs[ADIM];
    if (threadIdx.x < ADIM) qs[threadIdx.x] = g_q[b * ADIM + threadIdx.x];
    __syncthreads();

    float s = 0.f;
    #pragma unroll 8
    for (int a = 0; a < ADIM; a++) s += Wk[(size_t)a * HID + h] * qs[a];
    g_r[b * HID + h] = s * scale;
}

// ---------------------------------------------------------------------------
// Kernel 2: streaming pass over gene_hiddens (819 MB). One warp owns a
// contiguous row range; online-softmax weighted accumulation, 20 regs/lane.
// ---------------------------------------------------------------------------
__global__ void __launch_bounds__(256) k_pass1(const float* __restrict__ gh,
                                               int B, int N) {
    int wg   = blockIdx.x * 8 + (threadIdx.x >> 5);
    int b    = wg / WPB;
    int w    = wg % WPB;
    if (b >= B) return;
    int lane = threadIdx.x & 31;

    int rpw = (N + WPB - 1) / WPB;
    int n0  = w * rpw;
    int n1  = min(N, n0 + rpw);

    const float4* rb = reinterpret_cast<const float4*>(g_r + b * HID);
    float4 rr[5], acc[5];
    #pragma unroll
    for (int k = 0; k < 5; k++) {
        rr[k]  = rb[lane + 32 * k];
        acc[k] = make_float4(0.f, 0.f, 0.f, 0.f);
    }

    float m = -1e30f, s = 0.f;
    const float4* base = reinterpret_cast<const float4*>(gh) + (size_t)b * N * (HID / 4);

    for (int n = n0; n < n1; n++) {
        const float4* p = base + (size_t)n * (HID / 4);
        float4 hv[5];
        #pragma unroll
        for (int k = 0; k < 5; k++) hv[k] = __ldcs(p + lane + 32 * k);

        float d = 0.f;
        #pragma unroll
        for (int k = 0; k < 5; k++)
            d += hv[k].x * rr[k].x + hv[k].y * rr[k].y
               + hv[k].z * rr[k].z + hv[k].w * rr[k].w;
        #pragma unroll
        for (int o = 16; o > 0; o >>= 1) d += __shfl_xor_sync(0xffffffffu, d, o);

        if (d > m) {
            float c = __expf(m - d);   // first iter: exp(-huge) = 0
            s *= c;
            #pragma unroll
            for (int k = 0; k < 5; k++) {
                acc[k].x *= c; acc[k].y *= c; acc[k].z *= c; acc[k].w *= c;
            }
            m = d;
        }
        float wt = __expf(d - m);
        s += wt;
        #pragma unroll
        for (int k = 0; k < 5; k++) {
            acc[k].x += wt * hv[k].x; acc[k].y += wt * hv[k].y;
            acc[k].z += wt * hv[k].z; acc[k].w += wt * hv[k].w;
        }
    }

    float4* pa = reinterpret_cast<float4*>(g_pacc + (size_t)(b * WPB + w) * HID);
    #pragma unroll
    for (int k = 0; k < 5; k++) pa[lane + 32 * k] = acc[k];
    if (lane == 0) { g_pm[b * WPB + w] = m; g_ps[b * WPB + w] = s; }
}

// ---------------------------------------------------------------------------
// Kernel 3: per-batch combine + Wv matvec + LayerNorm
// ---------------------------------------------------------------------------
__device__ __forceinline__ float block_sum_640(float v, float* sred, int t) {
    int lane = t & 31, wid = t >> 5;            // 20 warps
    #pragma unroll
    for (int o = 16; o > 0; o >>= 1) v += __shfl_xor_sync(0xffffffffu, v, o);
    if (lane == 0) sred[wid] = v;
    __syncthreads();
    if (wid == 0) {
        float x = (lane < 20) ? sred[lane] : 0.f;
        #pragma unroll
        for (int o = 16; o > 0; o >>= 1) x += __shfl_xor_sync(0xffffffffu, x, o);
        if (lane == 0) sred[0] = x;
    }
    __syncthreads();
    float r = sred[0];
    __syncthreads();
    return r;
}

__global__ void __launch_bounds__(640) k_pass2(const float* __restrict__ Wv,
                                               const float* __restrict__ gamma,
                                               const float* __restrict__ beta,
                                               float* __restrict__ out) {
    int b = blockIdx.x;
    int t = threadIdx.x;                // 640 threads = 20 warps
    int lane = t & 31, wid = t >> 5;

    __shared__ float sred[32];
    __shared__ float wsm[WPB];
    __shared__ float pooled[HID];
    __shared__ float yv[HID];

    // ---- global max over WPB partial maxima ----
    float mv = (t < WPB) ? g_pm[b * WPB + t] : -1e30f;
    #pragma unroll
    for (int o = 16; o > 0; o >>= 1)
        mv = fmaxf(mv, __shfl_xor_sync(0xffffffffu, mv, o));
    if (lane == 0) sred[wid] = mv;
    __syncthreads();
    if (wid == 0) {
        float x = (lane < 20) ? sred[lane] : -1e30f;
        #pragma unroll
        for (int o = 16; o > 0; o >>= 1)
            x = fmaxf(x, __shfl_xor_sync(0xffffffffu, x, o));
        if (lane == 0) sred[0] = x;
    }
    __syncthreads();
    float M = sred[0];
    __syncthreads();

    // ---- per-partial rescale weights + total softmax denominator ----
    float sv = 0.f;
    if (t < WPB) {
        float wv_ = __expf(g_pm[b * WPB + t] - M);
        wsm[t] = wv_;
        sv = wv_ * g_ps[b * WPB + t];
    }
    float S = block_sum_640(sv, sred, t);

    // ---- pooled[h] = (1/S) * sum_i wsm[i] * pacc[b,i,h] ----
    float a = 0.f;
    const float* pa = g_pacc + (size_t)b * WPB * HID + t;
    #pragma unroll 4
    for (int i = 0; i < WPB; i++) a += wsm[i] * pa[(size_t)i * HID];
    pooled[t] = a / S;
    __syncthreads();

    // ---- y[v] = sum_h pooled[h] * Wv[v,h]  (one warp per output v) ----
    for (int v = wid * 32; v < wid * 32 + 32; v++) {
        const float* wr = Wv + (size_t)v * HID;
        float acc2 = 0.f;
        #pragma unroll
        for (int h = lane; h < HID; h += 32) acc2 += pooled[h] * wr[h];
        #pragma unroll
        for (int o = 16; o > 0; o >>= 1)
            acc2 += __shfl_xor_sync(0xffffffffu, acc2, o);
        if (lane == 0) yv[v] = acc2;
    }
    __syncthreads();

    // ---- LayerNorm over 640 ----
    float x = yv[t];
    float mean = block_sum_640(x, sred, t) * (1.f / HID);
    float dx = x - mean;
    float var = block_sum_640(dx * dx, sred, t) * (1.f / HID);
    out[b * HID + t] = dx * rsqrtf(var + 1e-5f) * gamma[t] + beta[t];
}

// ---------------------------------------------------------------------------
extern "C" void kernel_launch(void* const* d_in, const int* in_sizes, int n_in,
                              void* d_out, int out_size) {
    const float* gh    = (const float*)d_in[0];
    const float* pos   = (const float*)d_in[1];
    const float* Wq    = (const float*)d_in[2];
    const float* Wk    = (const float*)d_in[3];
    const float* Wv    = (const float*)d_in[4];
    const float* gamma = (const float*)d_in[5];
    const float* beta  = (const float*)d_in[6];
    float* out = (float*)d_out;

    int B = in_sizes[1] / HID;             // 16
    int N = in_sizes[0] / (B * HID);       // 20000
    float scale = 1.0f / sqrtf((float)ADIM);

    k_q<<<(B * ADIM) / 8, 256>>>(pos, Wq);            // 256 blocks
    k_r<<<dim3(B, HID / 160), 160>>>(Wk, scale);      // 64 blocks

    int total_warps = B * WPB;             // 2368
    int blocks = total_warps / 8;          // 296 blocks = exactly 2/SM
    k_pass1<<<blocks, 256>>>(gh, B, N);

    k_pass2<<<B, HID>>>(Wv, gamma, beta, out);
}